// round 15
// baseline (speedup 1.0000x reference)
#include <cuda_runtime.h>
#include <cuda_bf16.h>

#define N_NODES 50000
#define N_EDGES 800000
#define IN_DIM 128
#define HID_DIM 256
#define OUT_DIM 5
#define M_TILES 391
#define M_PAD (M_TILES * 128)   // 50048

// ---------------- scratch (device globals; no allocation allowed) -------------
__device__ int   g_cnt [N_NODES];              // zero-initialized; re-zeroed by k_agg2
__device__ int   g_off [N_NODES];
__device__ int   g_cur [N_NODES];
__device__ float g_inv [N_NODES];
__device__ int   g_nbr [N_EDGES];
__device__ __nv_bfloat16 g_ahi[M_PAD * 256];   // A = [mean | x], split hi
__device__ __nv_bfloat16 g_alo[M_PAD * 256];   // A split lo
__device__ __nv_bfloat16 g_bhi[256 * 256];     // B = [W1l ; W1r] concat, hi
__device__ __nv_bfloat16 g_blo[256 * 256];     // B lo
__device__ float g_h[N_NODES * HID_DIM];       // layer-1 output (fp32)
__device__ float g_p[N_NODES * 8];
__device__ float g_q[N_NODES * 8];

// ---------------- helpers -------------------------------------------------------
__device__ __forceinline__ unsigned smem_u32(const void* p) {
    unsigned a;
    asm("{ .reg .u64 t; cvta.to.shared.u64 t, %1; cvt.u32.u64 %0, t; }" : "=r"(a) : "l"(p));
    return a;
}
__device__ __forceinline__ void mma_bf16(float* c, const unsigned* a, const unsigned* b) {
    asm volatile(
        "mma.sync.aligned.m16n8k16.row.col.f32.bf16.bf16.f32 "
        "{%0,%1,%2,%3}, {%4,%5,%6,%7}, {%8,%9}, {%0,%1,%2,%3};"
        : "+f"(c[0]), "+f"(c[1]), "+f"(c[2]), "+f"(c[3])
        : "r"(a[0]), "r"(a[1]), "r"(a[2]), "r"(a[3]), "r"(b[0]), "r"(b[1]));
}
__device__ __forceinline__ void ldm_x4(unsigned* r, unsigned sa) {
    asm volatile("ldmatrix.sync.aligned.m8n8.x4.shared.b16 {%0,%1,%2,%3}, [%4];"
                 : "=r"(r[0]), "=r"(r[1]), "=r"(r[2]), "=r"(r[3]) : "r"(sa));
}

// split fp32x4 into bf16 hi/lo, 8-byte stores
__device__ __forceinline__ void split_store4(float4 v, __nv_bfloat16* hi, __nv_bfloat16* lo) {
    __nv_bfloat16 h0 = __float2bfloat16(v.x), h1 = __float2bfloat16(v.y);
    __nv_bfloat16 h2 = __float2bfloat16(v.z), h3 = __float2bfloat16(v.w);
    __nv_bfloat16 l0 = __float2bfloat16(v.x - __bfloat162float(h0));
    __nv_bfloat16 l1 = __float2bfloat16(v.y - __bfloat162float(h1));
    __nv_bfloat16 l2 = __float2bfloat16(v.z - __bfloat162float(h2));
    __nv_bfloat16 l3 = __float2bfloat16(v.w - __bfloat162float(h3));
    ushort4 H = make_ushort4(__bfloat16_as_ushort(h0), __bfloat16_as_ushort(h1),
                             __bfloat16_as_ushort(h2), __bfloat16_as_ushort(h3));
    ushort4 L = make_ushort4(__bfloat16_as_ushort(l0), __bfloat16_as_ushort(l1),
                             __bfloat16_as_ushort(l2), __bfloat16_as_ushort(l3));
    *reinterpret_cast<ushort4*>(hi) = H;
    *reinterpret_cast<ushort4*>(lo) = L;
}

// ---------------- CSR build ----------------------------------------------------
__global__ void k_hist(const int* __restrict__ ei) {
    int e = blockIdx.x * blockDim.x + threadIdx.x;
    if (e >= N_EDGES) return;
    atomicAdd(&g_cnt[ei[N_EDGES + e]], 1);
}
__global__ void __launch_bounds__(1024) k_scan() {
    const int PER = (N_NODES + 1023) / 1024;
    int t = threadIdx.x, beg = t * PER, end = min(beg + PER, N_NODES);
    int s = 0;
    for (int i = beg; i < end; ++i) s += g_cnt[i];
    __shared__ int sh[1024];
    sh[t] = s;
    __syncthreads();
    for (int d = 1; d < 1024; d <<= 1) {
        int v = (t >= d) ? sh[t - d] : 0;
        __syncthreads();
        sh[t] += v;
        __syncthreads();
    }
    int run = (t == 0) ? 0 : sh[t - 1];
    for (int i = beg; i < end; ++i) {
        int c = g_cnt[i];
        g_off[i] = run; g_cur[i] = run;
        g_inv[i] = 1.0f / (float)max(c, 1);
        run += c;
    }
}
__global__ void k_fill(const int* __restrict__ ei) {
    int e = blockIdx.x * blockDim.x + threadIdx.x;
    if (e >= N_EDGES) return;
    int pos = atomicAdd(&g_cur[ei[N_EDGES + e]], 1);
    g_nbr[pos] = ei[e];
}

// ---------------- layer-1 aggregation + x convert (fused) ----------------------
__global__ void __launch_bounds__(256) k_agg1(const float* __restrict__ x) {
    int node = (blockIdx.x * blockDim.x + threadIdx.x) >> 5;
    int lane = threadIdx.x & 31;
    if (node >= N_NODES) return;
    int off = g_off[node], cnt = g_cnt[node];
    const float4* x4 = reinterpret_cast<const float4*>(x);
    float4 acc = make_float4(0.f, 0.f, 0.f, 0.f);
    int j = 0;
    for (; j + 2 <= cnt; j += 2) {
        int s0 = g_nbr[off + j], s1 = g_nbr[off + j + 1];
        float4 v0 = x4[(size_t)s0 * 32 + lane];
        float4 v1 = x4[(size_t)s1 * 32 + lane];
        acc.x += v0.x + v1.x; acc.y += v0.y + v1.y;
        acc.z += v0.z + v1.z; acc.w += v0.w + v1.w;
    }
    if (j < cnt) {
        float4 v = x4[(size_t)g_nbr[off + j] * 32 + lane];
        acc.x += v.x; acc.y += v.y; acc.z += v.z; acc.w += v.w;
    }
    float inv = g_inv[node];
    acc.x *= inv; acc.y *= inv; acc.z *= inv; acc.w *= inv;
    size_t o = (size_t)node * 256 + lane * 4;          // cols 0..127 = mean
    split_store4(acc, g_ahi + o, g_alo + o);
    // fused convx: cols 128..255 = x[node]
    float4 xv = x4[(size_t)node * 32 + lane];
    split_store4(xv, g_ahi + o + 128, g_alo + o + 128);
}

// weights: B[n][k] = k<128 ? W1l[n][k] : W1r[n][k-128]  (bf16 hi/lo)
__global__ void __launch_bounds__(256) k_convw(const float* __restrict__ W1l,
                                               const float* __restrict__ W1r) {
    int i = blockIdx.x * blockDim.x + threadIdx.x;
    if (i >= 256 * 256) return;
    int n = i >> 8, k = i & 255;
    float v = (k < 128) ? W1l[n * 128 + k] : W1r[n * 128 + (k - 128)];
    __nv_bfloat16 h = __float2bfloat16(v);
    g_bhi[i] = h;
    g_blo[i] = __float2bfloat16(v - __bfloat162float(h));
}

// ---------------- layer-1 GEMM via warp mma.sync + ldmatrix --------------------
// grid (391, 2). BM=128, BN=128, BK=64, 256 thr = 8 warps (2 m x 4 n), 64x32/warp.
// Single-stage SMEM (73.7 KB -> 2 CTA/SM). Row stride 144 B: ldmatrix conflict-free.
#define STRIDE_B 144
#define OFF_AH 0
#define OFF_AL (OFF_AH + 128 * STRIDE_B)
#define OFF_BH (OFF_AL + 128 * STRIDE_B)
#define OFF_BL (OFF_BH + 128 * STRIDE_B)
#define GSMEM  (OFF_BL + 128 * STRIDE_B)   // 73728 B

__global__ void __launch_bounds__(256) k_gemm1_mma(const float* __restrict__ b1l) {
    extern __shared__ char smem[];
    unsigned sb = smem_u32(smem);
    int tid = threadIdx.x;
    int warp = tid >> 5, lane = tid & 31;
    int wm = warp >> 2;            // 0..1  (64 rows each)
    int wn = warp & 3;             // 0..3  (32 cols each)
    int g  = lane >> 2;            // 0..7
    int tg = lane & 3;             // 0..3
    int l15 = lane & 15;           // ldmatrix row within 16
    int lhi = lane >> 4;           // ldmatrix k-half (0/1)
    int tile = blockIdx.x;         // M tile
    int bn   = blockIdx.y;         // N tile (0..1)

    const uint4* AH = reinterpret_cast<const uint4*>(g_ahi);
    const uint4* AL = reinterpret_cast<const uint4*>(g_alo);
    const uint4* BH = reinterpret_cast<const uint4*>(g_bhi);
    const uint4* BL = reinterpret_cast<const uint4*>(g_blo);

    float acc[4][4][4] = {};

    for (int kc = 0; kc < 4; ++kc) {      // K chunks of 64
        __syncthreads();
        // fill SMEM: 128 rows x 8 uint4 for each of A/B hi/lo
        #pragma unroll
        for (int i = 0; i < 4; ++i) {
            int idx = tid + i * 256;       // 0..1023
            int row = idx >> 3, c8 = idx & 7;
            size_t gA = (size_t)(tile * 128 + row) * 32 + kc * 8 + c8;
            size_t gB = (size_t)(bn * 128 + row) * 32 + kc * 8 + c8;
            char* d = smem + row * STRIDE_B + c8 * 16;
            *reinterpret_cast<uint4*>(d + OFF_AH) = AH[gA];
            *reinterpret_cast<uint4*>(d + OFF_AL) = AL[gA];
            *reinterpret_cast<uint4*>(d + OFF_BH) = BH[gB];
            *reinterpret_cast<uint4*>(d + OFF_BL) = BL[gB];
        }
        __syncthreads();

        #pragma unroll
        for (int ks = 0; ks < 4; ++ks) {   // 4 k-steps of 16
            unsigned kboff = ks * 32 + lhi * 16;
            // A fragments via ldmatrix.x4 (rows m, cols k)
            unsigned a_addr = sb + (wm * 64 + l15) * STRIDE_B + kboff;
            unsigned ah[4][4], al[4][4];
            #pragma unroll
            for (int mt = 0; mt < 4; ++mt) {
                ldm_x4(ah[mt], a_addr + OFF_AH + mt * 16 * STRIDE_B);
                ldm_x4(al[mt], a_addr + OFF_AL + mt * 16 * STRIDE_B);
            }
            // B fragments: one x4 covers two adjacent n8 tiles for k16
            unsigned b_addr = sb + (wn * 32 + l15) * STRIDE_B + kboff;
            unsigned bhf[4][2], blf[4][2], t[4];
            #pragma unroll
            for (int p = 0; p < 2; ++p) {
                ldm_x4(t, b_addr + OFF_BH + p * 16 * STRIDE_B);
                bhf[2 * p][0] = t[0]; bhf[2 * p + 1][0] = t[1];
                bhf[2 * p][1] = t[2]; bhf[2 * p + 1][1] = t[3];
                ldm_x4(t, b_addr + OFF_BL + p * 16 * STRIDE_B);
                blf[2 * p][0] = t[0]; blf[2 * p + 1][0] = t[1];
                blf[2 * p][1] = t[2]; blf[2 * p + 1][1] = t[3];
            }
            #pragma unroll
            for (int mt = 0; mt < 4; ++mt)
                #pragma unroll
                for (int nt = 0; nt < 4; ++nt) {
                    mma_bf16(acc[mt][nt], ah[mt], bhf[nt]);   // hi*hi
                    mma_bf16(acc[mt][nt], ah[mt], blf[nt]);   // hi*lo
                    mma_bf16(acc[mt][nt], al[mt], bhf[nt]);   // lo*hi
                }
        }
    }

    // epilogue: bias + relu, write fp32 h
    #pragma unroll
    for (int mt = 0; mt < 4; ++mt) {
        int r0 = tile * 128 + wm * 64 + mt * 16 + g;
        #pragma unroll
        for (int nt = 0; nt < 4; ++nt) {
            int c = bn * 128 + wn * 32 + nt * 8 + tg * 2;
            float bx = b1l[c], by = b1l[c + 1];
            if (r0 < N_NODES) {
                float2 v = make_float2(fmaxf(acc[mt][nt][0] + bx, 0.f),
                                       fmaxf(acc[mt][nt][1] + by, 0.f));
                *reinterpret_cast<float2*>(g_h + (size_t)r0 * HID_DIM + c) = v;
            }
            if (r0 + 8 < N_NODES) {
                float2 v = make_float2(fmaxf(acc[mt][nt][2] + bx, 0.f),
                                       fmaxf(acc[mt][nt][3] + by, 0.f));
                *reinterpret_cast<float2*>(g_h + (size_t)(r0 + 8) * HID_DIM + c) = v;
            }
        }
    }
}

// ---------------- layer-2 projection: warp per node, coalesced -----------------
__global__ void __launch_bounds__(256)
k_gemm2(const float* __restrict__ W2l, const float* __restrict__ W2r) {
    __shared__ float ws[10][256];
    int tid = threadIdx.x;
    for (int i = tid; i < 5 * 256; i += 256) ws[i / 256][i % 256]     = W2l[i];
    for (int i = tid; i < 5 * 256; i += 256) ws[5 + i / 256][i % 256] = W2r[i];
    __syncthreads();

    int warp = tid >> 5, lane = tid & 31;
    int base = blockIdx.x * 256;

    for (int n = warp; n < 256; n += 8) {
        int node = base + n;
        if (node >= N_NODES) break;   // warp-uniform
        const float* hr = g_h + (size_t)node * HID_DIM;

        float h[8];
        #pragma unroll
        for (int t = 0; t < 8; ++t) h[t] = hr[lane + 32 * t];  // coalesced

        float acc[10];
        #pragma unroll
        for (int j = 0; j < 10; ++j) {
            float a = 0.f;
            #pragma unroll
            for (int t = 0; t < 8; ++t) a += h[t] * ws[j][lane + 32 * t];
            acc[j] = a;
        }
        #pragma unroll
        for (int j = 0; j < 10; ++j)
            #pragma unroll
            for (int o = 16; o; o >>= 1)
                acc[j] += __shfl_xor_sync(0xffffffffu, acc[j], o);

        if (lane < 5)             { g_p[node * 8 + lane] = acc[lane];
                                    g_q[node * 8 + lane] = acc[5 + lane]; }
        else if (lane < 8)        { g_p[node * 8 + lane] = 0.f;
                                    g_q[node * 8 + lane] = 0.f; }
    }
}

// ---------------- layer-2 aggregation + epilogue (also re-zeroes g_cnt) --------
__global__ void __launch_bounds__(256)
k_agg2(const float* __restrict__ b2l, float* __restrict__ out) {
    int node = (blockIdx.x * blockDim.x + threadIdx.x) >> 5;
    int lane = threadIdx.x & 31;
    if (node >= N_NODES) return;

    int c = lane & 7, g = lane >> 3;
    int off = g_off[node], cnt = g_cnt[node];

    float acc = 0.f;
    for (int j = g; j < cnt; j += 4)
        acc += g_p[g_nbr[off + j] * 8 + c];
    acc += __shfl_down_sync(0xffffffffu, acc, 16);
    acc += __shfl_down_sync(0xffffffffu, acc, 8);

    if (lane < OUT_DIM) {
        float v = acc * g_inv[node] + b2l[lane] + g_q[node * 8 + lane];
        out[(size_t)node * OUT_DIM + lane] = fmaxf(v, 0.f);
    }
    if (lane == 8) g_cnt[node] = 0;   // ready for next replay (zero-init at load)
}

// ---------------- launch -------------------------------------------------------
extern "C" void kernel_launch(void* const* d_in, const int* in_sizes, int n_in,
                              void* d_out, int out_size) {
    const float* x   = (const float*)d_in[0];
    const int*   ei  = (const int*)d_in[1];     // int32: [src | dst]
    const float* W1l = (const float*)d_in[2];
    const float* b1l = (const float*)d_in[3];
    const float* W1r = (const float*)d_in[4];
    const float* W2l = (const float*)d_in[5];
    const float* b2l = (const float*)d_in[6];
    const float* W2r = (const float*)d_in[7];
    float* out = (float*)d_out;

    cudaFuncSetAttribute(k_gemm1_mma, cudaFuncAttributeMaxDynamicSharedMemorySize,
                         GSMEM);

    k_hist<<<(N_EDGES + 255) / 256, 256>>>(ei);
    k_scan<<<1, 1024>>>();
    k_fill<<<(N_EDGES + 255) / 256, 256>>>(ei);
    k_agg1<<<(N_NODES * 32 + 255) / 256, 256>>>(x);
    k_convw<<<(256 * 256 + 255) / 256, 256>>>(W1l, W1r);
    k_gemm1_mma<<<dim3(M_TILES, 2), 256, GSMEM>>>(b1l);
    k_gemm2<<<(N_NODES + 255) / 256, 256>>>(W2l, W2r);
    k_agg2<<<(N_NODES * 32 + 255) / 256, 256>>>(b2l, out);
}

// round 16
// speedup vs baseline: 1.4123x; 1.4123x over previous
#include <cuda_runtime.h>
#include <cuda_bf16.h>

#define N_NODES 50000
#define N_EDGES 800000
#define IN_DIM 128
#define HID_DIM 256
#define OUT_DIM 5
#define M_TILES 391
#define M_PAD (M_TILES * 128)   // 50048

// ---------------- scratch (device globals; no allocation allowed) -------------
__device__ int   g_cnt [N_NODES];              // zero-initialized; re-zeroed by k_agg2
__device__ int   g_off [N_NODES];
__device__ int   g_cur [N_NODES];
__device__ float g_inv [N_NODES];
__device__ int   g_nbr [N_EDGES];
__device__ __nv_bfloat16 g_ahi[M_PAD * 256];   // A = [mean | x], split hi
__device__ __nv_bfloat16 g_alo[M_PAD * 256];   // A split lo
__device__ __nv_bfloat16 g_bhi[256 * 256];     // B = [W1l ; W1r] concat, hi
__device__ __nv_bfloat16 g_blo[256 * 256];     // B lo
__device__ float g_h[N_NODES * HID_DIM];       // layer-1 output (fp32)
__device__ float g_p[N_NODES * 8];
__device__ float g_q[N_NODES * 8];

// ---------------- helpers -------------------------------------------------------
__device__ __forceinline__ unsigned smem_u32(const void* p) {
    unsigned a;
    asm("{ .reg .u64 t; cvta.to.shared.u64 t, %1; cvt.u32.u64 %0, t; }" : "=r"(a) : "l"(p));
    return a;
}
__device__ __forceinline__ void cp16(unsigned sa, const void* g) {
    asm volatile("cp.async.ca.shared.global [%0], [%1], 16;" :: "r"(sa), "l"(g) : "memory");
}
#define CP_COMMIT() asm volatile("cp.async.commit_group;" ::: "memory")
#define CP_WAIT(n)  asm volatile("cp.async.wait_group %0;" :: "n"(n) : "memory")

__device__ __forceinline__ void mma_bf16(float* c, const unsigned* a, const unsigned* b) {
    asm volatile(
        "mma.sync.aligned.m16n8k16.row.col.f32.bf16.bf16.f32 "
        "{%0,%1,%2,%3}, {%4,%5,%6,%7}, {%8,%9}, {%0,%1,%2,%3};"
        : "+f"(c[0]), "+f"(c[1]), "+f"(c[2]), "+f"(c[3])
        : "r"(a[0]), "r"(a[1]), "r"(a[2]), "r"(a[3]), "r"(b[0]), "r"(b[1]));
}
__device__ __forceinline__ void ldm_x4(unsigned* r, unsigned sa) {
    asm volatile("ldmatrix.sync.aligned.m8n8.x4.shared.b16 {%0,%1,%2,%3}, [%4];"
                 : "=r"(r[0]), "=r"(r[1]), "=r"(r[2]), "=r"(r[3]) : "r"(sa));
}

// split fp32x4 into bf16 hi/lo, 8-byte stores
__device__ __forceinline__ void split_store4(float4 v, __nv_bfloat16* hi, __nv_bfloat16* lo) {
    __nv_bfloat16 h0 = __float2bfloat16(v.x), h1 = __float2bfloat16(v.y);
    __nv_bfloat16 h2 = __float2bfloat16(v.z), h3 = __float2bfloat16(v.w);
    __nv_bfloat16 l0 = __float2bfloat16(v.x - __bfloat162float(h0));
    __nv_bfloat16 l1 = __float2bfloat16(v.y - __bfloat162float(h1));
    __nv_bfloat16 l2 = __float2bfloat16(v.z - __bfloat162float(h2));
    __nv_bfloat16 l3 = __float2bfloat16(v.w - __bfloat162float(h3));
    ushort4 H = make_ushort4(__bfloat16_as_ushort(h0), __bfloat16_as_ushort(h1),
                             __bfloat16_as_ushort(h2), __bfloat16_as_ushort(h3));
    ushort4 L = make_ushort4(__bfloat16_as_ushort(l0), __bfloat16_as_ushort(l1),
                             __bfloat16_as_ushort(l2), __bfloat16_as_ushort(l3));
    *reinterpret_cast<ushort4*>(hi) = H;
    *reinterpret_cast<ushort4*>(lo) = L;
}

// ---------------- CSR build ----------------------------------------------------
__global__ void k_hist(const int* __restrict__ ei) {
    int e = blockIdx.x * blockDim.x + threadIdx.x;
    if (e >= N_EDGES) return;
    atomicAdd(&g_cnt[ei[N_EDGES + e]], 1);
}

// Coalesced scan: thread t owns nodes {t, t+1024, ...}. Segment order in the CSR
// is arbitrary (only off/cnt matter), so each thread assigns its nodes contiguous
// slots starting at its scanned base. All global accesses coalesced.
__global__ void __launch_bounds__(1024) k_scan() {
    int t = threadIdx.x;
    int s = 0;
    for (int i = t; i < N_NODES; i += 1024) s += g_cnt[i];

    __shared__ int sh[1024];
    sh[t] = s;
    __syncthreads();
    for (int d = 1; d < 1024; d <<= 1) {
        int v = (t >= d) ? sh[t - d] : 0;
        __syncthreads();
        sh[t] += v;
        __syncthreads();
    }
    int run = (t == 0) ? 0 : sh[t - 1];
    for (int i = t; i < N_NODES; i += 1024) {
        int c = g_cnt[i];
        g_off[i] = run; g_cur[i] = run;
        g_inv[i] = 1.0f / (float)max(c, 1);
        run += c;
    }
}

__global__ void k_fill(const int* __restrict__ ei) {
    int e = blockIdx.x * blockDim.x + threadIdx.x;
    if (e >= N_EDGES) return;
    int pos = atomicAdd(&g_cur[ei[N_EDGES + e]], 1);
    g_nbr[pos] = ei[e];
}

// ---------------- layer-1 aggregation + x convert (fused) ----------------------
__global__ void __launch_bounds__(256) k_agg1(const float* __restrict__ x) {
    int node = (blockIdx.x * blockDim.x + threadIdx.x) >> 5;
    int lane = threadIdx.x & 31;
    if (node >= N_NODES) return;
    int off = g_off[node], cnt = g_cnt[node];
    const float4* x4 = reinterpret_cast<const float4*>(x);
    float4 acc = make_float4(0.f, 0.f, 0.f, 0.f);
    int j = 0;
    for (; j + 2 <= cnt; j += 2) {
        int s0 = g_nbr[off + j], s1 = g_nbr[off + j + 1];
        float4 v0 = x4[(size_t)s0 * 32 + lane];
        float4 v1 = x4[(size_t)s1 * 32 + lane];
        acc.x += v0.x + v1.x; acc.y += v0.y + v1.y;
        acc.z += v0.z + v1.z; acc.w += v0.w + v1.w;
    }
    if (j < cnt) {
        float4 v = x4[(size_t)g_nbr[off + j] * 32 + lane];
        acc.x += v.x; acc.y += v.y; acc.z += v.z; acc.w += v.w;
    }
    float inv = g_inv[node];
    acc.x *= inv; acc.y *= inv; acc.z *= inv; acc.w *= inv;
    size_t o = (size_t)node * 256 + lane * 4;          // cols 0..127 = mean
    split_store4(acc, g_ahi + o, g_alo + o);
    // fused convx: cols 128..255 = x[node]
    float4 xv = x4[(size_t)node * 32 + lane];
    split_store4(xv, g_ahi + o + 128, g_alo + o + 128);
}

// weights: B[n][k] = k<128 ? W1l[n][k] : W1r[n][k-128]  (bf16 hi/lo)
__global__ void __launch_bounds__(256) k_convw(const float* __restrict__ W1l,
                                               const float* __restrict__ W1r) {
    int i = blockIdx.x * blockDim.x + threadIdx.x;
    if (i >= 256 * 256) return;
    int n = i >> 8, k = i & 255;
    float v = (k < 128) ? W1l[n * 128 + k] : W1r[n * 128 + (k - 128)];
    __nv_bfloat16 h = __float2bfloat16(v);
    g_bhi[i] = h;
    g_blo[i] = __float2bfloat16(v - __bfloat162float(h));
}

// ---------------- layer-1 GEMM: mma.sync + ldmatrix, BK=32 double-buffered -----
// grid (391, 2). BM=128, BN=128, 256 thr = 8 warps (2 m x 4 n), 64x32 per warp.
// Stage = 40 KB, 2 stages = 80 KB -> still multi-CTA/SM. Row stride 80 B:
// ldmatrix banks (20r mod 32) all-distinct over 8 rows => conflict-free.
#define STRIDE_B 80
#define OFF_AH 0
#define OFF_AL (OFF_AH + 128 * STRIDE_B)
#define OFF_BH (OFF_AL + 128 * STRIDE_B)
#define OFF_BL (OFF_BH + 128 * STRIDE_B)
#define STAGE  (OFF_BL + 128 * STRIDE_B)   // 40960 B
#define GSMEM  (2 * STAGE)                 // 81920 B

__global__ void __launch_bounds__(256) k_gemm1_mma(const float* __restrict__ b1l) {
    extern __shared__ char smem[];
    unsigned sb = smem_u32(smem);
    int tid = threadIdx.x;
    int warp = tid >> 5, lane = tid & 31;
    int wm = warp >> 2;            // 0..1  (64 rows each)
    int wn = warp & 3;             // 0..3  (32 cols each)
    int g  = lane >> 2;            // 0..7
    int tg = lane & 3;             // 0..3
    int l15 = lane & 15;
    int lhi = lane >> 4;
    int tile = blockIdx.x;         // M tile
    int bn   = blockIdx.y;         // N tile (0..1)

    const uint4* AH = reinterpret_cast<const uint4*>(g_ahi);
    const uint4* AL = reinterpret_cast<const uint4*>(g_alo);
    const uint4* BH = reinterpret_cast<const uint4*>(g_bhi);
    const uint4* BL = reinterpret_cast<const uint4*>(g_blo);

    // per chunk: A/B 128 rows x 32 cols (4 uint4/row) per array; 512 uint4 each
    auto prefetch = [&](int kc, int buf) {
        unsigned base = sb + buf * STAGE;
        #pragma unroll
        for (int i = 0; i < 2; ++i) {
            int idx = tid + i * 256;       // 0..511
            int row = idx >> 2, c4 = idx & 3;
            size_t gA = (size_t)(tile * 128 + row) * 32 + kc * 4 + c4;
            size_t gB = (size_t)(bn * 128 + row) * 32 + kc * 4 + c4;
            unsigned d = base + row * STRIDE_B + c4 * 16;
            cp16(d + OFF_AH, AH + gA);
            cp16(d + OFF_AL, AL + gA);
            cp16(d + OFF_BH, BH + gB);
            cp16(d + OFF_BL, BL + gB);
        }
    };

    float acc[4][4][4] = {};

    prefetch(0, 0);
    CP_COMMIT();

    for (int kc = 0; kc < 8; ++kc) {      // K chunks of 32
        __syncthreads();                  // protect buffer (kc+1)&1 from in-flight readers
        if (kc < 7) {
            prefetch(kc + 1, (kc + 1) & 1);
            CP_COMMIT();
            CP_WAIT(1);
        } else {
            CP_WAIT(0);
        }
        __syncthreads();
        unsigned sm = sb + (kc & 1) * STAGE;

        #pragma unroll
        for (int ks = 0; ks < 2; ++ks) {   // 2 k-steps of 16
            unsigned kboff = ks * 32 + lhi * 16;
            unsigned a_addr = sm + (wm * 64 + l15) * STRIDE_B + kboff;
            unsigned ah[4][4], al[4][4];
            #pragma unroll
            for (int mt = 0; mt < 4; ++mt) {
                ldm_x4(ah[mt], a_addr + OFF_AH + mt * 16 * STRIDE_B);
                ldm_x4(al[mt], a_addr + OFF_AL + mt * 16 * STRIDE_B);
            }
            unsigned b_addr = sm + (wn * 32 + l15) * STRIDE_B + kboff;
            unsigned bhf[4][2], blf[4][2], t[4];
            #pragma unroll
            for (int p = 0; p < 2; ++p) {
                ldm_x4(t, b_addr + OFF_BH + p * 16 * STRIDE_B);
                bhf[2 * p][0] = t[0]; bhf[2 * p + 1][0] = t[1];
                bhf[2 * p][1] = t[2]; bhf[2 * p + 1][1] = t[3];
                ldm_x4(t, b_addr + OFF_BL + p * 16 * STRIDE_B);
                blf[2 * p][0] = t[0]; blf[2 * p + 1][0] = t[1];
                blf[2 * p][1] = t[2]; blf[2 * p + 1][1] = t[3];
            }
            #pragma unroll
            for (int mt = 0; mt < 4; ++mt)
                #pragma unroll
                for (int nt = 0; nt < 4; ++nt) {
                    mma_bf16(acc[mt][nt], ah[mt], bhf[nt]);   // hi*hi
                    mma_bf16(acc[mt][nt], ah[mt], blf[nt]);   // hi*lo
                    mma_bf16(acc[mt][nt], al[mt], bhf[nt]);   // lo*hi
                }
        }
    }

    // epilogue: bias + relu, write fp32 h
    #pragma unroll
    for (int mt = 0; mt < 4; ++mt) {
        int r0 = tile * 128 + wm * 64 + mt * 16 + g;
        #pragma unroll
        for (int nt = 0; nt < 4; ++nt) {
            int c = bn * 128 + wn * 32 + nt * 8 + tg * 2;
            float bx = b1l[c], by = b1l[c + 1];
            if (r0 < N_NODES) {
                float2 v = make_float2(fmaxf(acc[mt][nt][0] + bx, 0.f),
                                       fmaxf(acc[mt][nt][1] + by, 0.f));
                *reinterpret_cast<float2*>(g_h + (size_t)r0 * HID_DIM + c) = v;
            }
            if (r0 + 8 < N_NODES) {
                float2 v = make_float2(fmaxf(acc[mt][nt][2] + bx, 0.f),
                                       fmaxf(acc[mt][nt][3] + by, 0.f));
                *reinterpret_cast<float2*>(g_h + (size_t)(r0 + 8) * HID_DIM + c) = v;
            }
        }
    }
}

// ---------------- layer-2 projection: warp per node, coalesced -----------------
__global__ void __launch_bounds__(256)
k_gemm2(const float* __restrict__ W2l, const float* __restrict__ W2r) {
    __shared__ float ws[10][256];
    int tid = threadIdx.x;
    for (int i = tid; i < 5 * 256; i += 256) ws[i / 256][i % 256]     = W2l[i];
    for (int i = tid; i < 5 * 256; i += 256) ws[5 + i / 256][i % 256] = W2r[i];
    __syncthreads();

    int warp = tid >> 5, lane = tid & 31;
    int base = blockIdx.x * 256;

    for (int n = warp; n < 256; n += 8) {
        int node = base + n;
        if (node >= N_NODES) break;   // warp-uniform
        const float* hr = g_h + (size_t)node * HID_DIM;

        float h[8];
        #pragma unroll
        for (int t = 0; t < 8; ++t) h[t] = hr[lane + 32 * t];  // coalesced

        float acc[10];
        #pragma unroll
        for (int j = 0; j < 10; ++j) {
            float a = 0.f;
            #pragma unroll
            for (int t = 0; t < 8; ++t) a += h[t] * ws[j][lane + 32 * t];
            acc[j] = a;
        }
        #pragma unroll
        for (int j = 0; j < 10; ++j)
            #pragma unroll
            for (int o = 16; o; o >>= 1)
                acc[j] += __shfl_xor_sync(0xffffffffu, acc[j], o);

        if (lane < 5)             { g_p[node * 8 + lane] = acc[lane];
                                    g_q[node * 8 + lane] = acc[5 + lane]; }
        else if (lane < 8)        { g_p[node * 8 + lane] = 0.f;
                                    g_q[node * 8 + lane] = 0.f; }
    }
}

// ---------------- layer-2 aggregation + epilogue (also re-zeroes g_cnt) --------
__global__ void __launch_bounds__(256)
k_agg2(const float* __restrict__ b2l, float* __restrict__ out) {
    int node = (blockIdx.x * blockDim.x + threadIdx.x) >> 5;
    int lane = threadIdx.x & 31;
    if (node >= N_NODES) return;

    int c = lane & 7, g = lane >> 3;
    int off = g_off[node], cnt = g_cnt[node];

    float acc = 0.f;
    for (int j = g; j < cnt; j += 4)
        acc += g_p[g_nbr[off + j] * 8 + c];
    acc += __shfl_down_sync(0xffffffffu, acc, 16);
    acc += __shfl_down_sync(0xffffffffu, acc, 8);

    if (lane < OUT_DIM) {
        float v = acc * g_inv[node] + b2l[lane] + g_q[node * 8 + lane];
        out[(size_t)node * OUT_DIM + lane] = fmaxf(v, 0.f);
    }
    if (lane == 8) g_cnt[node] = 0;   // ready for next replay (zero-init at load)
}

// ---------------- launch -------------------------------------------------------
extern "C" void kernel_launch(void* const* d_in, const int* in_sizes, int n_in,
                              void* d_out, int out_size) {
    const float* x   = (const float*)d_in[0];
    const int*   ei  = (const int*)d_in[1];     // int32: [src | dst]
    const float* W1l = (const float*)d_in[2];
    const float* b1l = (const float*)d_in[3];
    const float* W1r = (const float*)d_in[4];
    const float* W2l = (const float*)d_in[5];
    const float* b2l = (const float*)d_in[6];
    const float* W2r = (const float*)d_in[7];
    float* out = (float*)d_out;

    cudaFuncSetAttribute(k_gemm1_mma, cudaFuncAttributeMaxDynamicSharedMemorySize,
                         GSMEM);

    k_hist<<<(N_EDGES + 255) / 256, 256>>>(ei);
    k_scan<<<1, 1024>>>();
    k_fill<<<(N_EDGES + 255) / 256, 256>>>(ei);
    k_agg1<<<(N_NODES * 32 + 255) / 256, 256>>>(x);
    k_convw<<<(256 * 256 + 255) / 256, 256>>>(W1l, W1r);
    k_gemm1_mma<<<dim3(M_TILES, 2), 256, GSMEM>>>(b1l);
    k_gemm2<<<(N_NODES + 255) / 256, 256>>>(W2l, W2r);
    k_agg2<<<(N_NODES * 32 + 255) / 256, 256>>>(b2l, out);
}